// round 6
// baseline (speedup 1.0000x reference)
#include <cuda_runtime.h>

// ---------------------------------------------------------------------------
// Problem: B=8, H=126, W=126, F=64, D=32; grids padded 128x128.
// Plane-major layout: field[(b*32+d)][r][c]; 256 independent planes.
// Fused sim: 256 CTAs x 256 thr, 2 CTAs/SM (single wave).
// ---------------------------------------------------------------------------
constexpr double dDX  = 2.0 / 9.0;
constexpr double dDY  = 2.0 / 127.0;
constexpr double dDX2 = dDX * dDX;
constexpr double dDY2 = dDY * dDY;
constexpr double dDEN = 2.0 * (dDX2 + dDY2);

#define F_A    ((float)(dDY2 / dDEN))        // coeff for E/W
#define F_B    ((float)(dDX2 / dDEN))        // coeff for N/S
#define F_CB   ((float)(dDX2 * dDY2 / dDEN))
#define F_I2DX ((float)(1.0 / (2.0 * dDX)))
#define F_I2DY ((float)(1.0 / (2.0 * dDY)))
#define F_IDT  (10.0f)
#define F_DTDX ((float)(0.1 / dDX))
#define F_DTDY ((float)(0.1 / dDY))
#define F_PGX  ((float)(0.1 / (2.0 * dDX)))
#define F_PGY  ((float)(0.1 / (2.0 * dDY)))
#define F_NUX  ((float)(0.01 / dDX2))
#define F_NUY  ((float)(0.01 / dDY2))
#define F_FDT  (0.1f)

#define NPLANE_F  (128 * 128)
#define NPLANE_F4 (NPLANE_F / 4)
#define NTOT_F    (256 * NPLANE_F)

__device__ float g_pT[NTOT_F];
__device__ float g_uT[NTOT_F];
__device__ float g_vT[NTOT_F];
__device__ float g_uA[NTOT_F];
__device__ float g_vA[NTOT_F];
__device__ float g_uB[NTOT_F];
__device__ float g_vB[NTOT_F];

// ---------------------------------------------------------------------------
// Packed f32x2 helpers
// ---------------------------------------------------------------------------
typedef unsigned long long ull;
__device__ __forceinline__ ull pk2(float lo, float hi) {
    ull r;
    asm("mov.b64 %0, {%1, %2};" : "=l"(r) : "f"(lo), "f"(hi));
    return r;
}
__device__ __forceinline__ void fma2(ull& acc, ull a, ull b) {
    asm("fma.rn.f32x2 %0, %1, %2, %0;" : "+l"(acc) : "l"(a), "l"(b));
}
__device__ __forceinline__ float lo32(ull v) { return __uint_as_float((unsigned)v); }
__device__ __forceinline__ float hi32(ull v) { return __uint_as_float((unsigned)(v >> 32)); }

__device__ __forceinline__ float4 unpk(ulonglong2 p) {
    return make_float4(lo32(p.x), hi32(p.x), lo32(p.y), hi32(p.y));
}
__device__ __forceinline__ ulonglong2 pk4(float4 v) {
    ulonglong2 r; r.x = pk2(v.x, v.y); r.y = pk2(v.z, v.w); return r;
}

// ---------------------------------------------------------------------------
// init_p: p[(b,d)][r][c] = sum_f xpad[b,r,c,f]*w[d,f] + b_lin[d]
// ---------------------------------------------------------------------------
__global__ __launch_bounds__(256) void init_p(
    const float* __restrict__ x, const float* __restrict__ wm,
    const float* __restrict__ bl, float* __restrict__ pT)
{
    __shared__ __align__(16) float  xs[128][68];
    __shared__ __align__(16) float2 wsp[16][64];
    __shared__ float bls[32];

    int r = blockIdx.x, b = blockIdx.y;
    int tid = threadIdx.x;

    if (tid < 32) bls[tid] = bl[tid];
    for (int i = tid; i < 16 * 64; i += 256) {
        int dp = i >> 6, f = i & 63;
        wsp[dp][f] = make_float2(wm[(2 * dp) * 64 + f], wm[(2 * dp + 1) * 64 + f]);
    }

    bool border_r = (r == 0 || r == 127);
    if (!border_r) {
        for (int i = tid; i < 128 * 64; i += 256) {
            int c = i >> 6, f = i & 63;
            float val = 0.0f;
            if (c >= 1 && c <= 126)
                val = x[((b * 126 + (r - 1)) * 126 + (c - 1)) * 64 + f];
            xs[c][f] = val;
        }
    }
    __syncthreads();

    if (border_r) {
        for (int i = tid; i < 32 * 128; i += 256) {
            int d = i >> 7, c = i & 127;
            pT[((b * 32 + d) * 128 + r) * 128 + c] = bls[d];
        }
        return;
    }

    int lane = tid & 31;
    int wz   = tid >> 5;
    int dp0  = 2 * wz;

    ull acc[2][4];
#pragma unroll
    for (int dp = 0; dp < 2; dp++)
#pragma unroll
        for (int j = 0; j < 4; j++) acc[dp][j] = 0ULL;

#pragma unroll 4
    for (int fc = 0; fc < 16; fc++) {
        float4 xv[4];
#pragma unroll
        for (int j = 0; j < 4; j++)
            xv[j] = reinterpret_cast<const float4*>(&xs[lane + 32 * j][0])[fc];

        ulonglong2 wA0 = *reinterpret_cast<const ulonglong2*>(&wsp[dp0][4 * fc]);
        ulonglong2 wB0 = *reinterpret_cast<const ulonglong2*>(&wsp[dp0][4 * fc + 2]);
        ulonglong2 wA1 = *reinterpret_cast<const ulonglong2*>(&wsp[dp0 + 1][4 * fc]);
        ulonglong2 wB1 = *reinterpret_cast<const ulonglong2*>(&wsp[dp0 + 1][4 * fc + 2]);
        ull w0[4] = { wA0.x, wA0.y, wB0.x, wB0.y };
        ull w1[4] = { wA1.x, wA1.y, wB1.x, wB1.y };

#pragma unroll
        for (int j = 0; j < 4; j++) {
            const float* xvf = reinterpret_cast<const float*>(&xv[j]);
#pragma unroll
            for (int k = 0; k < 4; k++) {
                ull xx = pk2(xvf[k], xvf[k]);
                fma2(acc[0][j], xx, w0[k]);
                fma2(acc[1][j], xx, w1[k]);
            }
        }
    }

#pragma unroll
    for (int dp = 0; dp < 2; dp++) {
        int d = 4 * wz + 2 * dp;
        float bl0 = bls[d], bl1 = bls[d + 1];
#pragma unroll
        for (int j = 0; j < 4; j++) {
            int c = lane + 32 * j;
            pT[((b * 32 + d)     * 128 + r) * 128 + c] = lo32(acc[dp][j]) + bl0;
            pT[((b * 32 + d + 1) * 128 + r) * 128 + c] = hi32(acc[dp][j]) + bl1;
        }
    }
}

// ---------------------------------------------------------------------------
// transpose u0/v0: [b][r][c][d] -> [(b*32+d)][r][c]
// ---------------------------------------------------------------------------
__global__ __launch_bounds__(256) void transpose_uv(
    const float* __restrict__ u0, const float* __restrict__ v0,
    float* __restrict__ uT, float* __restrict__ vT)
{
    __shared__ float t[128][33];
    int r = blockIdx.x, b = blockIdx.y;
    const float* src = (blockIdx.z == 0) ? u0 : v0;
    float*       dst = (blockIdx.z == 0) ? uT : vT;

    for (int i = threadIdx.x; i < 4096; i += 256) {
        int c = i >> 5, d = i & 31;
        t[c][d] = src[((b * 128 + r) * 128 + c) * 32 + d];
    }
    __syncthreads();
    for (int i = threadIdx.x; i < 4096; i += 256) {
        int d = i >> 7, c = i & 127;
        dst[((b * 32 + d) * 128 + r) * 128 + c] = t[c][d];
    }
}

// ---------------------------------------------------------------------------
// Fused sim: 1 CTA = 1 plane, 256 thr = 8 warps, warp owns rows 16w..16w+15,
// lane owns cols 4l..4l+3. P packed f32x2 in registers; C in smem; halo smem.
// smem: C 128x32 ulonglong2 (64 KB) + halo 2x8x2x32 ulonglong2 (16 KB) = 80 KB
// ---------------------------------------------------------------------------
extern __shared__ ulonglong2 dsm[];
#define CSM(r, l)          dsm[(r) * 32 + (l)]
#define HL(buf, w, tb, l)  dsm[4096 + ((((buf) * 8 + (w)) * 2 + (tb)) * 32) + (l)]

__device__ __forceinline__ ulonglong2 jrow2(
    ulonglong2 cur, ulonglong2 N, ulonglong2 S, ulonglong2 C,
    ull Apk, ull Bpk, int laneW, int laneE)
{
    float cy = hi32(cur.x), cz = lo32(cur.y);
    ull eyz = pk2(cy, cz);                               // (y,z): E-of-lo, W-of-hi
    float w0 = __shfl_sync(0xffffffffu, hi32(cur.y), laneW);
    float e3 = __shfl_sync(0xffffffffu, lo32(cur.x), laneE);
    ull wlo = pk2(w0, lo32(cur.x));                      // (w0, x)
    ull ehi = pk2(hi32(cur.y), e3);                      // (w, e3)
    ull olo = C.x, ohi = C.y;
    fma2(olo, N.x, Bpk); fma2(olo, S.x, Bpk);
    fma2(olo, eyz, Apk); fma2(olo, wlo, Apk);
    fma2(ohi, N.y, Bpk); fma2(ohi, S.y, Bpk);
    fma2(ohi, ehi, Apk); fma2(ohi, eyz, Apk);
    ulonglong2 o; o.x = olo; o.y = ohi; return o;
}

__global__ __launch_bounds__(256, 2) void fused_sim(
    const float4* __restrict__ pT,
    const float4* __restrict__ uT, const float4* __restrict__ vT,
    float4* __restrict__ uA, float4* __restrict__ vA,
    float4* __restrict__ uB, float4* __restrict__ vB,
    float* __restrict__ out)
{
    int bd   = blockIdx.x;
    int tid  = threadIdx.x;
    int lane = tid & 31;
    int wid  = tid >> 5;
    int r0   = wid << 4;                   // 16 rows per warp
    int laneW = (lane + 31) & 31;
    int laneE = (lane + 1) & 31;
    const bool topw = (wid == 0);
    const bool botw = (wid == 7);

    const ull Apk = pk2(F_A, F_A);
    const ull Bpk = pk2(F_B, F_B);

    // ---- load p rows into packed registers ----
    const float4* pP = pT + (size_t)bd * NPLANE_F4;
    ulonglong2 P[16];
#pragma unroll
    for (int i = 0; i < 16; i++) P[i] = pk4(pP[(r0 + i) * 32 + lane]);

    const float4* uc_ = uT + (size_t)bd * NPLANE_F4;
    const float4* vc_ = vT + (size_t)bd * NPLANE_F4;

    for (int it = 0; it < 3; it++) {
        // ---------------- build_b -> C smem (coalesced global reads) ------
#pragma unroll 4
        for (int i = 0; i < 16; i++) {
            int r = r0 + i;
            if (r < 1 || r > 126) continue;
            float4 uo = uc_[r * 32 + lane];
            float4 un = uc_[(r - 1) * 32 + lane];
            float4 us = uc_[(r + 1) * 32 + lane];
            float4 vo = vc_[r * 32 + lane];
            float4 vn = vc_[(r - 1) * 32 + lane];
            float4 vs = vc_[(r + 1) * 32 + lane];
            float uw0 = __shfl_sync(0xffffffffu, uo.w, laneW);
            float ue3 = __shfl_sync(0xffffffffu, uo.x, laneE);
            float vw0 = __shfl_sync(0xffffffffu, vo.w, laneW);
            float ve3 = __shfl_sync(0xffffffffu, vo.x, laneE);
            float4 cv;
#define BQ(q, UW, UE, VW, VE) { \
            float dudx = (UE - UW) * F_I2DX; \
            float dvdy = (vs.q - vn.q) * F_I2DY; \
            float dudy = (us.q - un.q) * F_I2DY; \
            float dvdx = (VE - VW) * F_I2DX; \
            float bv = (dudx + dvdy) * F_IDT - dudx * dudx \
                     - 2.0f * dudy * dvdx - dvdy * dvdy; \
            cv.q = -F_CB * bv; }
            BQ(x, uw0,  uo.y, vw0,  vo.y)
            BQ(y, uo.x, uo.z, vo.x, vo.z)
            BQ(z, uo.y, uo.w, vo.y, vo.w)
            BQ(w, uo.z, ue3,  vo.z, ve3)
#undef BQ
            CSM(r, lane) = pk4(cv);
        }

        // ---------------- 20 Jacobi sweeps --------------------------------
        HL(0, wid, 0, lane) = P[0];
        HL(0, wid, 1, lane) = P[15];
        for (int s = 0; s < 20; s++) {
            __syncthreads();
            int hb = s & 1;
            ulonglong2 o1 = P[1], o14 = P[14];
            ulonglong2 oldN = P[0];
#pragma unroll
            for (int i = 1; i <= 14; i++) {
                ulonglong2 cur = P[i];
                P[i] = jrow2(cur, oldN, P[i + 1], CSM(r0 + i, lane),
                             Apk, Bpk, laneW, laneE);
                oldN = cur;
            }
            if (!botw) {
                ulonglong2 hS = HL(hb, wid + 1, 0, lane);
                P[15] = jrow2(P[15], o14, hS, CSM(r0 + 15, lane),
                              Apk, Bpk, laneW, laneE);
            } else {
                P[15] = P[14];
            }
            if (!topw) {
                ulonglong2 hN = HL(hb, wid - 1, 1, lane);
                P[0] = jrow2(P[0], hN, o1, CSM(r0, lane),
                             Apk, Bpk, laneW, laneE);
            } else {
                P[0] = P[1];
            }
            HL(hb ^ 1, wid, 0, lane) = P[0];
            HL(hb ^ 1, wid, 1, lane) = P[15];
        }
        __syncthreads();   // final publish visible; sweeps done

        // ---------------- velocity (it 0,1; it 2's result is dead) --------
        if (it < 2) {
            float4* unG = ((it == 0) ? uA : uB) + (size_t)bd * NPLANE_F4;
            float4* vnG = ((it == 0) ? vA : vB) + (size_t)bd * NPLANE_F4;
            float4 z4 = make_float4(0.f, 0.f, 0.f, 0.f);
            float4 phN = topw ? z4 : unpk(HL(0, wid - 1, 1, lane));
            float4 phS = botw ? z4 : unpk(HL(0, wid + 1, 0, lane));

#pragma unroll 4
            for (int i = 0; i < 16; i++) {
                int r = r0 + i;
                if (r < 1 || r > 126) {
                    unG[r * 32 + lane] = z4;
                    vnG[r * 32 + lane] = z4;
                    continue;
                }
                float4 uo = uc_[r * 32 + lane];
                float4 un = uc_[(r - 1) * 32 + lane];
                float4 us = uc_[(r + 1) * 32 + lane];
                float4 vo = vc_[r * 32 + lane];
                float4 vn = vc_[(r - 1) * 32 + lane];
                float4 vs = vc_[(r + 1) * 32 + lane];
                float4 pN = (i > 0)  ? unpk(P[i - 1]) : phN;
                float4 pS = (i < 15) ? unpk(P[i + 1]) : phS;
                float4 po = unpk(P[i]);
                float uw0 = __shfl_sync(0xffffffffu, uo.w, laneW);
                float ue3 = __shfl_sync(0xffffffffu, uo.x, laneE);
                float vw0 = __shfl_sync(0xffffffffu, vo.w, laneW);
                float ve3 = __shfl_sync(0xffffffffu, vo.x, laneE);
                float pw0 = __shfl_sync(0xffffffffu, po.w, laneW);
                float pe3 = __shfl_sync(0xffffffffu, po.x, laneE);
                float4 ru, rv;
#define VQ(q, UW, UE, VW, VE, PW, PE) { \
                float uc = uo.q, vc = vo.q; \
                ru.q = uc - uc * F_DTDX * (uc - UW) - vc * F_DTDY * (uc - un.q) \
                     - F_PGX * (PE - PW) \
                     + F_NUX * (UE - 2.0f * uc + UW) + F_NUY * (us.q - 2.0f * uc + un.q) \
                     + F_FDT; \
                rv.q = vc - uc * F_DTDX * (vc - VW) - vc * F_DTDY * (vc - vn.q) \
                     - F_PGY * (pS.q - pN.q) \
                     + F_NUX * (VE - 2.0f * vc + VW) + F_NUY * (vs.q - 2.0f * vc + vn.q); }
                VQ(x, uw0,  uo.y, vw0,  vo.y, pw0,  po.y)
                VQ(y, uo.x, uo.z, vo.x, vo.z, po.x, po.z)
                VQ(z, uo.y, uo.w, vo.y, vo.w, po.y, po.w)
                VQ(w, uo.z, ue3,  vo.z, ve3,  po.z, pe3)
#undef VQ
                unG[r * 32 + lane] = ru;
                vnG[r * 32 + lane] = rv;
            }
            __syncthreads();   // u,v writes visible block-wide (global, same CTA)
            uc_ = unG;
            vc_ = vnG;
        }
    }

    // ---- output: out[(b*128 + c)*32 + d] = p[row 127][c] ----
    if (botw) {
        int b = bd >> 5, d = bd & 31;
        int cb = lane << 2;
        float4 v = unpk(P[15]);
        out[((b << 7) + cb + 0) * 32 + d] = v.x;
        out[((b << 7) + cb + 1) * 32 + d] = v.y;
        out[((b << 7) + cb + 2) * 32 + d] = v.z;
        out[((b << 7) + cb + 3) * 32 + d] = v.w;
    }
}

// ---------------------------------------------------------------------------
// Host driver
// ---------------------------------------------------------------------------
extern "C" void kernel_launch(void* const* d_in, const int* in_sizes, int n_in,
                              void* d_out, int out_size)
{
    const float* x    = (const float*)d_in[0];
    const float* u0   = (const float*)d_in[1];
    const float* v0   = (const float*)d_in[2];
    const float* wm   = (const float*)d_in[3];
    const float* blin = (const float*)d_in[4];

    float *pT, *uT, *vT, *uA, *vA, *uB, *vB;
    cudaGetSymbolAddress((void**)&pT, g_pT);
    cudaGetSymbolAddress((void**)&uT, g_uT);
    cudaGetSymbolAddress((void**)&vT, g_vT);
    cudaGetSymbolAddress((void**)&uA, g_uA);
    cudaGetSymbolAddress((void**)&vA, g_vA);
    cudaGetSymbolAddress((void**)&uB, g_uB);
    cudaGetSymbolAddress((void**)&vB, g_vB);

    const int SMEM = 5120 * (int)sizeof(ulonglong2);   // 80 KB
    cudaFuncSetAttribute(fused_sim, cudaFuncAttributeMaxDynamicSharedMemorySize, SMEM);

    transpose_uv<<<dim3(128, 8, 2), 256>>>(u0, v0, uT, vT);
    init_p<<<dim3(128, 8), 256>>>(x, wm, blin, pT);

    fused_sim<<<256, 256, SMEM>>>(
        (const float4*)pT, (const float4*)uT, (const float4*)vT,
        (float4*)uA, (float4*)vA, (float4*)uB, (float4*)vB,
        (float*)d_out);
}

// round 7
// speedup vs baseline: 1.2010x; 1.2010x over previous
#include <cuda_runtime.h>

// ---------------------------------------------------------------------------
// Problem: B=8, H=126, W=126, F=64, D=32; grids padded 128x128.
// p is plane-major: p[(b*32+d)][r][c]; u,v read directly from [b][r][c][d].
// 256 independent (b,d) planes after the init GEMM.
// ---------------------------------------------------------------------------
constexpr double dDX  = 2.0 / 9.0;
constexpr double dDY  = 2.0 / 127.0;
constexpr double dDX2 = dDX * dDX;
constexpr double dDY2 = dDY * dDY;
constexpr double dDEN = 2.0 * (dDX2 + dDY2);

#define F_A    ((float)(dDY2 / dDEN))        // coeff for E/W
#define F_B    ((float)(dDX2 / dDEN))        // coeff for N/S
#define F_CB   ((float)(dDX2 * dDY2 / dDEN))
#define F_I2DX ((float)(1.0 / (2.0 * dDX)))
#define F_I2DY ((float)(1.0 / (2.0 * dDY)))
#define F_IDT  (10.0f)
#define F_DTDX ((float)(0.1 / dDX))
#define F_DTDY ((float)(0.1 / dDY))
#define F_PGX  ((float)(0.1 / (2.0 * dDX)))
#define F_PGY  ((float)(0.1 / (2.0 * dDY)))
#define F_NUX  ((float)(0.01 / dDX2))
#define F_NUY  ((float)(0.01 / dDY2))
#define F_FDT  (0.1f)

#define NPLANE_F  (128 * 128)
#define NPLANE_F4 (NPLANE_F / 4)
#define NTOT_F    (256 * NPLANE_F)

__device__ float g_pT[NTOT_F];

// ---------------------------------------------------------------------------
// Packed f32x2 helpers (init GEMM)
// ---------------------------------------------------------------------------
typedef unsigned long long ull;
__device__ __forceinline__ ull pk2(float lo, float hi) {
    ull r;
    asm("mov.b64 %0, {%1, %2};" : "=l"(r) : "f"(lo), "f"(hi));
    return r;
}
__device__ __forceinline__ void fma2(ull& acc, ull a, ull b) {
    asm("fma.rn.f32x2 %0, %1, %2, %0;" : "+l"(acc) : "l"(a), "l"(b));
}
__device__ __forceinline__ float lo32(ull v) { return __uint_as_float((unsigned)v); }
__device__ __forceinline__ float hi32(ull v) { return __uint_as_float((unsigned)(v >> 32)); }

// ---------------------------------------------------------------------------
// init_p: p[(b,d)][r][c] = sum_f xpad[b,r,c,f]*w[d,f] + b_lin[d]
// ---------------------------------------------------------------------------
__global__ __launch_bounds__(256) void init_p(
    const float* __restrict__ x, const float* __restrict__ wm,
    const float* __restrict__ bl, float* __restrict__ pT)
{
    __shared__ __align__(16) float  xs[128][68];
    __shared__ __align__(16) float2 wsp[16][64];
    __shared__ float bls[32];

    int r = blockIdx.x, b = blockIdx.y;
    int tid = threadIdx.x;

    if (tid < 32) bls[tid] = bl[tid];
    for (int i = tid; i < 16 * 64; i += 256) {
        int dp = i >> 6, f = i & 63;
        wsp[dp][f] = make_float2(wm[(2 * dp) * 64 + f], wm[(2 * dp + 1) * 64 + f]);
    }

    bool border_r = (r == 0 || r == 127);
    if (!border_r) {
        for (int i = tid; i < 128 * 64; i += 256) {
            int c = i >> 6, f = i & 63;
            float val = 0.0f;
            if (c >= 1 && c <= 126)
                val = x[((b * 126 + (r - 1)) * 126 + (c - 1)) * 64 + f];
            xs[c][f] = val;
        }
    }
    __syncthreads();

    if (border_r) {
        for (int i = tid; i < 32 * 128; i += 256) {
            int d = i >> 7, c = i & 127;
            pT[((b * 32 + d) * 128 + r) * 128 + c] = bls[d];
        }
        return;
    }

    int lane = tid & 31;
    int wz   = tid >> 5;
    int dp0  = 2 * wz;

    ull acc[2][4];
#pragma unroll
    for (int dp = 0; dp < 2; dp++)
#pragma unroll
        for (int j = 0; j < 4; j++) acc[dp][j] = 0ULL;

#pragma unroll 4
    for (int fc = 0; fc < 16; fc++) {
        float4 xv[4];
#pragma unroll
        for (int j = 0; j < 4; j++)
            xv[j] = reinterpret_cast<const float4*>(&xs[lane + 32 * j][0])[fc];

        ulonglong2 wA0 = *reinterpret_cast<const ulonglong2*>(&wsp[dp0][4 * fc]);
        ulonglong2 wB0 = *reinterpret_cast<const ulonglong2*>(&wsp[dp0][4 * fc + 2]);
        ulonglong2 wA1 = *reinterpret_cast<const ulonglong2*>(&wsp[dp0 + 1][4 * fc]);
        ulonglong2 wB1 = *reinterpret_cast<const ulonglong2*>(&wsp[dp0 + 1][4 * fc + 2]);
        ull w0[4] = { wA0.x, wA0.y, wB0.x, wB0.y };
        ull w1[4] = { wA1.x, wA1.y, wB1.x, wB1.y };

#pragma unroll
        for (int j = 0; j < 4; j++) {
            const float* xvf = reinterpret_cast<const float*>(&xv[j]);
#pragma unroll
            for (int k = 0; k < 4; k++) {
                ull xx = pk2(xvf[k], xvf[k]);
                fma2(acc[0][j], xx, w0[k]);
                fma2(acc[1][j], xx, w1[k]);
            }
        }
    }

#pragma unroll
    for (int dp = 0; dp < 2; dp++) {
        int d = 4 * wz + 2 * dp;
        float bl0 = bls[d], bl1 = bls[d + 1];
#pragma unroll
        for (int j = 0; j < 4; j++) {
            int c = lane + 32 * j;
            pT[((b * 32 + d)     * 128 + r) * 128 + c] = lo32(acc[dp][j]) + bl0;
            pT[((b * 32 + d + 1) * 128 + r) * 128 + c] = hi32(acc[dp][j]) + bl1;
        }
    }
}

// ---------------------------------------------------------------------------
// Fused sim: 1 CTA = 1 plane. 512 thr = 16 warps; warp w owns rows 8w..8w+7,
// lane owns cols 4l..4l+3. p and -CB*b in registers; u,v smem-resident.
// Jacobi sweep: interior rows BEFORE the barrier (register-only work hides
// barrier convergence); double-buffered halo, one barrier per sweep.
// Dynamic smem: u (4096 f4) + v (4096 f4) + halo (2048 f4) = 160 KB.
// ---------------------------------------------------------------------------
extern __shared__ float4 dynsm[];
#define SMU(r, l) dynsm[(r) * 32 + (l)]
#define SMV(r, l) dynsm[4096 + (r) * 32 + (l)]
#define HL(buf, w, tb, l) dynsm[8192 + ((((buf) * 16 + (w)) * 2 + (tb)) * 32) + (l)]

// interior row: chain C -> S -> N -> W -> E (all register operands)
__device__ __forceinline__ float4 jrow(float4 cur, float4 N, float4 S, float4 C,
                                       int laneW, int laneE) {
    float w0 = __shfl_sync(0xffffffffu, cur.w, laneW);
    float e3 = __shfl_sync(0xffffffffu, cur.x, laneE);
    float4 o;
    o.x = __fmaf_rn(cur.y, F_A, __fmaf_rn(w0,   F_A, __fmaf_rn(N.x, F_B, __fmaf_rn(S.x, F_B, C.x))));
    o.y = __fmaf_rn(cur.z, F_A, __fmaf_rn(cur.x, F_A, __fmaf_rn(N.y, F_B, __fmaf_rn(S.y, F_B, C.y))));
    o.z = __fmaf_rn(cur.w, F_A, __fmaf_rn(cur.y, F_A, __fmaf_rn(N.z, F_B, __fmaf_rn(S.z, F_B, C.z))));
    o.w = __fmaf_rn(e3,    F_A, __fmaf_rn(cur.z, F_A, __fmaf_rn(N.w, F_B, __fmaf_rn(S.w, F_B, C.w))));
    return o;
}

// boundary row: halo operand H applied LAST (shortest LDS->result path).
// Other neighbor R (register) applied first.
__device__ __forceinline__ float4 jrowH(float4 cur, float4 R, float4 H, float4 C,
                                        int laneW, int laneE) {
    float w0 = __shfl_sync(0xffffffffu, cur.w, laneW);
    float e3 = __shfl_sync(0xffffffffu, cur.x, laneE);
    float4 o;
    o.x = __fmaf_rn(H.x, F_B, __fmaf_rn(cur.y, F_A, __fmaf_rn(w0,   F_A, __fmaf_rn(R.x, F_B, C.x))));
    o.y = __fmaf_rn(H.y, F_B, __fmaf_rn(cur.z, F_A, __fmaf_rn(cur.x, F_A, __fmaf_rn(R.y, F_B, C.y))));
    o.z = __fmaf_rn(H.z, F_B, __fmaf_rn(cur.w, F_A, __fmaf_rn(cur.y, F_A, __fmaf_rn(R.z, F_B, C.z))));
    o.w = __fmaf_rn(H.w, F_B, __fmaf_rn(e3,    F_A, __fmaf_rn(cur.z, F_A, __fmaf_rn(R.w, F_B, C.w))));
    return o;
}

__global__ __launch_bounds__(512) void fused_sim(
    const float4* __restrict__ pT,
    const float* __restrict__ u0, const float* __restrict__ v0,
    float* __restrict__ out)
{
    int bd   = blockIdx.x;
    int tid  = threadIdx.x;
    int lane = tid & 31;
    int wid  = tid >> 5;
    int r0   = wid << 3;
    int laneW = (lane + 31) & 31;
    int laneE = (lane + 1) & 31;
    const bool topw = (wid == 0);
    const bool botw = (wid == 15);

    // ---- gather u,v planes (strided over d) into smem; p into registers ----
    {
        int b = bd >> 5, d = bd & 31;
        const float* uB = u0 + (size_t)b * (128 * 128 * 32) + d;
        const float* vB = v0 + (size_t)b * (128 * 128 * 32) + d;
        int c0 = lane << 2;
#pragma unroll
        for (int i = 0; i < 8; i++) {
            int r = r0 + i;
            const float* ru = uB + r * 4096;
            const float* rv = vB + r * 4096;
            float4 uu, vv;
            uu.x = __ldg(ru + (c0 + 0) * 32); uu.y = __ldg(ru + (c0 + 1) * 32);
            uu.z = __ldg(ru + (c0 + 2) * 32); uu.w = __ldg(ru + (c0 + 3) * 32);
            vv.x = __ldg(rv + (c0 + 0) * 32); vv.y = __ldg(rv + (c0 + 1) * 32);
            vv.z = __ldg(rv + (c0 + 2) * 32); vv.w = __ldg(rv + (c0 + 3) * 32);
            SMU(r, lane) = uu;
            SMV(r, lane) = vv;
        }
    }
    const float4* pP = pT + (size_t)bd * NPLANE_F4;
    float4 P[8];
#pragma unroll
    for (int i = 0; i < 8; i++) P[i] = pP[(r0 + i) * 32 + lane];
    __syncthreads();

    float4 C[8];

    for (int it = 0; it < 3; it++) {
        // ---------------- build_b -> C registers (smem reads) --------------
#pragma unroll
        for (int i = 0; i < 8; i++) {
            int r = r0 + i;
            if (r < 1 || r > 126) continue;
            float4 uo = SMU(r, lane), un = SMU(r - 1, lane), us = SMU(r + 1, lane);
            float4 vo = SMV(r, lane), vn = SMV(r - 1, lane), vs = SMV(r + 1, lane);
            float uw0 = __shfl_sync(0xffffffffu, uo.w, laneW);
            float ue3 = __shfl_sync(0xffffffffu, uo.x, laneE);
            float vw0 = __shfl_sync(0xffffffffu, vo.w, laneW);
            float ve3 = __shfl_sync(0xffffffffu, vo.x, laneE);
            float4 cv;
#define BQ(q, UW, UE, VW, VE) { \
            float dudx = (UE - UW) * F_I2DX; \
            float dvdy = (vs.q - vn.q) * F_I2DY; \
            float dudy = (us.q - un.q) * F_I2DY; \
            float dvdx = (VE - VW) * F_I2DX; \
            float bv = (dudx + dvdy) * F_IDT - dudx * dudx \
                     - 2.0f * dudy * dvdx - dvdy * dvdy; \
            cv.q = -F_CB * bv; }
            BQ(x, uw0,  uo.y, vw0,  vo.y)
            BQ(y, uo.x, uo.z, vo.x, vo.z)
            BQ(z, uo.y, uo.w, vo.y, vo.w)
            BQ(w, uo.z, ue3,  vo.z, ve3)
#undef BQ
            C[i] = cv;
        }

        // ---------------- 20 Jacobi sweeps, interior-before-barrier --------
        HL(0, wid, 0, lane) = P[0];
        HL(0, wid, 1, lane) = P[7];

#define SWEEP(RB, WB) { \
            float4 oP1 = P[1], oP6 = P[6]; \
            float4 oldN = P[0]; \
            _Pragma("unroll") \
            for (int i = 1; i <= 6; i++) { \
                float4 cur = P[i]; \
                P[i] = jrow(cur, oldN, P[i + 1], C[i], laneW, laneE); \
                oldN = cur; \
            } \
            __syncthreads(); \
            if (!botw) { \
                float4 hS = HL(RB, wid + 1, 0, lane); \
                P[7] = jrowH(P[7], oP6, hS, C[7], laneW, laneE); \
            } else { \
                P[7] = P[6]; \
            } \
            if (!topw) { \
                float4 hN = HL(RB, wid - 1, 1, lane); \
                P[0] = jrowH(P[0], oP1, hN, C[0], laneW, laneE); \
            } else { \
                P[0] = P[1]; \
            } \
            HL(WB, wid, 0, lane) = P[0]; \
            HL(WB, wid, 1, lane) = P[7]; \
        }

#pragma unroll 1
        for (int s = 0; s < 10; s++) {
            SWEEP(0, 1)
            SWEEP(1, 0)
        }
#undef SWEEP
        __syncthreads();   // final publish (buf0) visible

        // ---------------- velocity (it 0,1; it 2's result is dead) --------
        if (it < 2) {
            float4 z4 = make_float4(0.f, 0.f, 0.f, 0.f);
            float4 uNc = z4, vNc = z4, uSc = z4, vSc = z4;
            if (!topw) { uNc = SMU(r0 - 1, lane); vNc = SMV(r0 - 1, lane); }
            if (!botw) { uSc = SMU(r0 + 8, lane); vSc = SMV(r0 + 8, lane); }
            float4 phN = (!topw) ? HL(0, wid - 1, 1, lane) : P[0];
            float4 phS = (!botw) ? HL(0, wid + 1, 0, lane) : P[7];
            __syncthreads();   // all pre-reads done before in-place writes

            float4 unr = uNc, vnr = vNc;
#pragma unroll
            for (int i = 0; i < 8; i++) {
                int r = r0 + i;
                float4 uo = SMU(r, lane);
                float4 vo = SMV(r, lane);
                if (r >= 1 && r <= 126) {
                    float4 us = (i < 7) ? SMU(r + 1, lane) : uSc;
                    float4 vs = (i < 7) ? SMV(r + 1, lane) : vSc;
                    float4 pN = (i > 0) ? P[i - 1] : phN;
                    float4 pS = (i < 7) ? P[i + 1] : phS;
                    float4 po = P[i];
                    float uw0 = __shfl_sync(0xffffffffu, uo.w, laneW);
                    float ue3 = __shfl_sync(0xffffffffu, uo.x, laneE);
                    float vw0 = __shfl_sync(0xffffffffu, vo.w, laneW);
                    float ve3 = __shfl_sync(0xffffffffu, vo.x, laneE);
                    float pw0 = __shfl_sync(0xffffffffu, po.w, laneW);
                    float pe3 = __shfl_sync(0xffffffffu, po.x, laneE);
                    float4 ru, rv;
#define VQ(q, UW, UE, VW, VE, PW, PE) { \
                    float uc = uo.q, vc = vo.q; \
                    ru.q = uc - uc * F_DTDX * (uc - UW) - vc * F_DTDY * (uc - unr.q) \
                         - F_PGX * (PE - PW) \
                         + F_NUX * (UE - 2.0f * uc + UW) + F_NUY * (us.q - 2.0f * uc + unr.q) \
                         + F_FDT; \
                    rv.q = vc - uc * F_DTDX * (vc - VW) - vc * F_DTDY * (vc - vnr.q) \
                         - F_PGY * (pS.q - pN.q) \
                         + F_NUX * (VE - 2.0f * vc + VW) + F_NUY * (vs.q - 2.0f * vc + vnr.q); }
                    VQ(x, uw0,  uo.y, vw0,  vo.y, pw0,  po.y)
                    VQ(y, uo.x, uo.z, vo.x, vo.z, po.x, po.z)
                    VQ(z, uo.y, uo.w, vo.y, vo.w, po.y, po.w)
                    VQ(w, uo.z, ue3,  vo.z, ve3,  po.z, pe3)
#undef VQ
                    SMU(r, lane) = ru;
                    SMV(r, lane) = rv;
                } else {
                    SMU(r, lane) = z4;
                    SMV(r, lane) = z4;
                }
                unr = uo;
                vnr = vo;
            }
            __syncthreads();   // new u,v visible for next build_b
        }
    }

    // ---- output: out[(b*128 + c)*32 + d] = p[row 127][c] ----
    if (botw) {
        int b = bd >> 5, d = bd & 31;
        int cb = lane << 2;
        out[((b << 7) + cb + 0) * 32 + d] = P[7].x;
        out[((b << 7) + cb + 1) * 32 + d] = P[7].y;
        out[((b << 7) + cb + 2) * 32 + d] = P[7].z;
        out[((b << 7) + cb + 3) * 32 + d] = P[7].w;
    }
}

// ---------------------------------------------------------------------------
// Host driver
// ---------------------------------------------------------------------------
extern "C" void kernel_launch(void* const* d_in, const int* in_sizes, int n_in,
                              void* d_out, int out_size)
{
    const float* x    = (const float*)d_in[0];
    const float* u0   = (const float*)d_in[1];
    const float* v0   = (const float*)d_in[2];
    const float* wm   = (const float*)d_in[3];
    const float* blin = (const float*)d_in[4];

    float* pT;
    cudaGetSymbolAddress((void**)&pT, g_pT);

    cudaFuncSetAttribute(fused_sim, cudaFuncAttributeMaxDynamicSharedMemorySize,
                         10240 * (int)sizeof(float4));

    init_p<<<dim3(128, 8), 256>>>(x, wm, blin, pT);

    fused_sim<<<256, 512, 10240 * sizeof(float4)>>>(
        (const float4*)pT, u0, v0, (float*)d_out);
}